// round 1
// baseline (speedup 1.0000x reference)
#include <cuda_runtime.h>
#include <mma.h>
#include <math.h>
#include <stdint.h>

using namespace nvcuda;

#define D_EMB 1024
#define NB 8
#define SQ 577
#define SK 13271
#define LNEPS 1e-5f

// ---------------- scratch (__device__ globals; no allocations allowed) -------
__device__ float g_normX[(size_t)NB * SK * D_EMB];   // LN(input_features)  ~435MB
__device__ float g_normQ[(size_t)NB * SQ * D_EMB];   // LN(query)
__device__ float g_S   [(size_t)NB * SQ * SK];       // cross scores / probs ~245MB
__device__ float g_att [(size_t)NB * SQ * D_EMB];    // attended
__device__ float g_cross[(size_t)NB * SQ * D_EMB];   // cross_attended (MLP out)
__device__ float g_normC[(size_t)NB * SQ * D_EMB];   // LN(cross)
__device__ float g_S2  [(size_t)NB * SQ * SQ];       // self scores / probs
__device__ float g_self[(size_t)NB * SQ * D_EMB];    // self_attended

// ---------------- reductions (blockDim == 256) ------------------------------
__device__ __forceinline__ float block_sum(float v, float* red) {
    #pragma unroll
    for (int o = 16; o > 0; o >>= 1) v += __shfl_xor_sync(0xffffffffu, v, o);
    int w = threadIdx.x >> 5;
    if ((threadIdx.x & 31) == 0) red[w] = v;
    __syncthreads();
    float s = 0.f;
    #pragma unroll
    for (int i = 0; i < 8; i++) s += red[i];
    __syncthreads();
    return s;
}

__device__ __forceinline__ float block_max(float v, float* red) {
    #pragma unroll
    for (int o = 16; o > 0; o >>= 1) v = fmaxf(v, __shfl_xor_sync(0xffffffffu, v, o));
    int w = threadIdx.x >> 5;
    if ((threadIdx.x & 31) == 0) red[w] = v;
    __syncthreads();
    float s = -INFINITY;
    #pragma unroll
    for (int i = 0; i < 8; i++) s = fmaxf(s, red[i]);
    __syncthreads();
    return s;
}

// ---------------- layernorm: one block (256 thr) per 1024-elem row ----------
__global__ void ln_kernel(const float* __restrict__ in, const float* __restrict__ w,
                          const float* __restrict__ b, float* __restrict__ out) {
    __shared__ float red[8];
    size_t row = blockIdx.x;
    const float4* inr = (const float4*)(in + row * D_EMB);
    float4 v = inr[threadIdx.x];
    float s = v.x + v.y + v.z + v.w;
    float mean = block_sum(s, red) * (1.f / D_EMB);
    float dx = v.x - mean, dy = v.y - mean, dz = v.z - mean, dw = v.w - mean;
    float ss = dx*dx + dy*dy + dz*dz + dw*dw;
    float var = block_sum(ss, red) * (1.f / D_EMB);
    float inv = rsqrtf(var + LNEPS);
    float4 w4 = ((const float4*)w)[threadIdx.x];
    float4 b4 = ((const float4*)b)[threadIdx.x];
    float4 o;
    o.x = dx * inv * w4.x + b4.x;
    o.y = dy * inv * w4.y + b4.y;
    o.z = dz * inv * w4.z + b4.z;
    o.w = dw * inv * w4.w + b4.w;
    ((float4*)(out + row * D_EMB))[threadIdx.x] = o;
}

// ---------------- row softmax, in place -------------------------------------
__global__ void softmax_kernel(float* __restrict__ S, int n) {
    __shared__ float red[8];
    size_t row = blockIdx.x;
    float* p = S + row * (size_t)n;
    float m = -INFINITY;
    for (int i = threadIdx.x; i < n; i += 256) m = fmaxf(m, p[i]);
    m = block_max(m, red);
    float s = 0.f;
    for (int i = threadIdx.x; i < n; i += 256) s += __expf(p[i] - m);
    s = block_sum(s, red);
    float inv = 1.f / s;
    for (int i = threadIdx.x; i < n; i += 256) p[i] = __expf(p[i] - m) * inv;
}

// ---------------- tf32 wmma GEMM --------------------------------------------
// C[m][n] = alpha * sum_k A[m][k] * Bop[k][n]
// TRANS_B=true : B is [N,K] row-major (Bop = B^T)   -- used for Q·K^T
// TRANS_B=false: B is [K,N] row-major               -- used for P·V
template <bool TRANS_B>
__global__ void gemm_tf32(const float* __restrict__ A, const float* __restrict__ B,
                          float* __restrict__ C, int M, int N, int K,
                          size_t sA, size_t sB, size_t sC, float alpha) {
    constexpr int BM = 64, BN = 128, BK = 32;
    __shared__ float As[BM][BK + 4];      // ldm 36
    __shared__ float Bs[BK][BN + 4];      // ldm 132
    __shared__ float stage[8][16][16];    // per-warp store staging

    A += blockIdx.z * sA;  B += blockIdx.z * sB;  C += blockIdx.z * sC;
    int m0 = blockIdx.y * BM, n0 = blockIdx.x * BN;
    int tid = threadIdx.x, warp = tid >> 5, lid = tid & 31;
    int wm = warp >> 2, wn = warp & 3;    // warp grid 2 x 4, 32x32 per warp

    wmma::fragment<wmma::accumulator, 16, 16, 8, float> acc[2][2];
    #pragma unroll
    for (int i = 0; i < 2; i++)
        #pragma unroll
        for (int j = 0; j < 2; j++) wmma::fill_fragment(acc[i][j], 0.f);

    for (int k0 = 0; k0 < K; k0 += BK) {
        // A tile: 64x32, coalesced (one warp per row)
        #pragma unroll
        for (int x = 0; x < 8; x++) {
            int idx = tid + x * 256;
            int r = idx >> 5, c = idx & 31;
            int gr = m0 + r, gc = k0 + c;
            As[r][c] = (gr < M && gc < K) ? A[(size_t)gr * K + gc] : 0.f;
        }
        // B tile
        if (TRANS_B) {
            #pragma unroll
            for (int x = 0; x < 16; x++) {
                int idx = tid + x * 256;          // 128 n-rows x 32 k-cols
                int nn = idx >> 5, kk = idx & 31;
                int gn = n0 + nn, gk = k0 + kk;
                Bs[kk][nn] = (gn < N && gk < K) ? B[(size_t)gn * K + gk] : 0.f;
            }
        } else {
            #pragma unroll
            for (int x = 0; x < 16; x++) {
                int idx = tid + x * 256;          // 32 k-rows x 128 n-cols
                int kk = idx >> 7, nn = idx & 127;
                int gk = k0 + kk, gn = n0 + nn;
                Bs[kk][nn] = (gk < K && gn < N) ? B[(size_t)gk * N + gn] : 0.f;
            }
        }
        __syncthreads();
        #pragma unroll
        for (int ks = 0; ks < BK; ks += 8) {
            wmma::fragment<wmma::matrix_a, 16, 16, 8, wmma::precision::tf32, wmma::row_major> af[2];
            wmma::fragment<wmma::matrix_b, 16, 16, 8, wmma::precision::tf32, wmma::row_major> bf[2];
            #pragma unroll
            for (int i = 0; i < 2; i++) {
                wmma::load_matrix_sync(af[i], &As[wm * 32 + i * 16][ks], BK + 4);
                #pragma unroll
                for (int e = 0; e < af[i].num_elements; e++)
                    af[i].x[e] = wmma::__float_to_tf32(af[i].x[e]);
            }
            #pragma unroll
            for (int j = 0; j < 2; j++) {
                wmma::load_matrix_sync(bf[j], &Bs[ks][wn * 32 + j * 16], BN + 4);
                #pragma unroll
                for (int e = 0; e < bf[j].num_elements; e++)
                    bf[j].x[e] = wmma::__float_to_tf32(bf[j].x[e]);
            }
            #pragma unroll
            for (int i = 0; i < 2; i++)
                #pragma unroll
                for (int j = 0; j < 2; j++)
                    wmma::mma_sync(acc[i][j], af[i], bf[j], acc[i][j]);
        }
        __syncthreads();
    }

    // store (via smem staging: handles edges and odd ldc like 13271)
    #pragma unroll
    for (int i = 0; i < 2; i++)
        #pragma unroll
        for (int j = 0; j < 2; j++) {
            int rg = m0 + wm * 32 + i * 16, cg = n0 + wn * 32 + j * 16;
            #pragma unroll
            for (int e = 0; e < acc[i][j].num_elements; e++) acc[i][j].x[e] *= alpha;
            wmma::store_matrix_sync(&stage[warp][0][0], acc[i][j], 16, wmma::mem_row_major);
            __syncwarp();
            for (int e = lid; e < 256; e += 32) {
                int rr = e >> 4, cc = e & 15;
                if (rg + rr < M && cg + cc < N)
                    C[(size_t)(rg + rr) * N + (cg + cc)] = stage[warp][rr][cc];
            }
            __syncwarp();
        }
}

// ---------------- fused MLP (D->4->D, exact-erf GELU), 1 block / row --------
__global__ void mlp_kernel(const float* __restrict__ att, const float* __restrict__ w1,
                           const float* __restrict__ b1, const float* __restrict__ w2,
                           const float* __restrict__ b2, float* __restrict__ out) {
    __shared__ float red[4][8];
    __shared__ float hh[4];
    size_t row = blockIdx.x;
    float4 v = ((const float4*)(att + row * D_EMB))[threadIdx.x];
    float p[4];
    #pragma unroll
    for (int h = 0; h < 4; h++) {
        float4 w = ((const float4*)(w1 + (size_t)h * D_EMB))[threadIdx.x];
        p[h] = v.x * w.x + v.y * w.y + v.z * w.z + v.w * w.w;
        #pragma unroll
        for (int o = 16; o > 0; o >>= 1) p[h] += __shfl_xor_sync(0xffffffffu, p[h], o);
        if ((threadIdx.x & 31) == 0) red[h][threadIdx.x >> 5] = p[h];
    }
    __syncthreads();
    if (threadIdx.x < 4) {
        float s = b1[threadIdx.x];
        #pragma unroll
        for (int i = 0; i < 8; i++) s += red[threadIdx.x][i];
        hh[threadIdx.x] = 0.5f * s * (1.f + erff(s * 0.70710678118654752f));
    }
    __syncthreads();
    float h0 = hh[0], h1 = hh[1], h2 = hh[2], h3 = hh[3];
    float4 o;
    {
        int d = threadIdx.x * 4;
        float4 wa = ((const float4*)w2)[d + 0];
        float4 wb = ((const float4*)w2)[d + 1];
        float4 wc = ((const float4*)w2)[d + 2];
        float4 wd = ((const float4*)w2)[d + 3];
        o.x = h0 * wa.x + h1 * wa.y + h2 * wa.z + h3 * wa.w + b2[d + 0];
        o.y = h0 * wb.x + h1 * wb.y + h2 * wb.z + h3 * wb.w + b2[d + 1];
        o.z = h0 * wc.x + h1 * wc.y + h2 * wc.z + h3 * wc.w + b2[d + 2];
        o.w = h0 * wd.x + h1 * wd.y + h2 * wd.z + h3 * wd.w + b2[d + 3];
    }
    ((float4*)(out + row * D_EMB))[threadIdx.x] = o;
}

// ---------------- final combine: out = normQ + g2*(cross + g1*self) ---------
__global__ void final_kernel(const float* __restrict__ normQ, const float* __restrict__ cross,
                             const float* __restrict__ selfa, const float* __restrict__ g1,
                             const float* __restrict__ g2, float* __restrict__ out) {
    size_t i = (size_t)blockIdx.x * 256 + threadIdx.x;   // float4 index; 256/row
    float4 q = ((const float4*)normQ)[i];
    float4 c = ((const float4*)cross)[i];
    float4 s = ((const float4*)selfa)[i];
    float4 a = ((const float4*)g1)[threadIdx.x];
    float4 b = ((const float4*)g2)[threadIdx.x];
    float4 o;
    o.x = q.x + b.x * (c.x + a.x * s.x);
    o.y = q.y + b.y * (c.y + a.y * s.y);
    o.z = q.z + b.z * (c.z + a.z * s.z);
    o.w = q.w + b.w * (c.w + a.w * s.w);
    ((float4*)out)[i] = o;
}

// ---------------- launch ------------------------------------------------------
extern "C" void kernel_launch(void* const* d_in, const int* in_sizes, int n_in,
                              void* d_out, int out_size) {
    const float* input_features = (const float*)d_in[0];
    const float* query_feature  = (const float*)d_in[1];
    const float* n1w = (const float*)d_in[2];
    const float* n1b = (const float*)d_in[3];
    const float* n2w = (const float*)d_in[4];
    const float* n2b = (const float*)d_in[5];
    const float* n3w = (const float*)d_in[6];
    const float* n3b = (const float*)d_in[7];
    const float* g1  = (const float*)d_in[8];
    const float* g2  = (const float*)d_in[9];
    const float* fc1w = (const float*)d_in[10];
    const float* fc1b = (const float*)d_in[11];
    const float* fc2w = (const float*)d_in[12];
    const float* fc2b = (const float*)d_in[13];

    float *normX, *normQ, *S, *att, *cross, *normC, *S2, *selfa;
    cudaGetSymbolAddress((void**)&normX, g_normX);
    cudaGetSymbolAddress((void**)&normQ, g_normQ);
    cudaGetSymbolAddress((void**)&S,     g_S);
    cudaGetSymbolAddress((void**)&att,   g_att);
    cudaGetSymbolAddress((void**)&cross, g_cross);
    cudaGetSymbolAddress((void**)&normC, g_normC);
    cudaGetSymbolAddress((void**)&S2,    g_S2);
    cudaGetSymbolAddress((void**)&selfa, g_self);

    const float scale = 0.03125f;   // 1024^-0.5

    // 1) layernorms of inputs
    ln_kernel<<<NB * SK, 256>>>(input_features, n1w, n1b, normX);
    ln_kernel<<<NB * SQ, 256>>>(query_feature,  n2w, n2b, normQ);

    // 2) cross attention: S = normQ @ normX^T * scale
    gemm_tf32<true><<<dim3((SK + 127) / 128, (SQ + 63) / 64, NB), 256>>>(
        normQ, normX, S, SQ, SK, D_EMB,
        (size_t)SQ * D_EMB, (size_t)SK * D_EMB, (size_t)SQ * SK, scale);
    softmax_kernel<<<NB * SQ, 256>>>(S, SK);
    gemm_tf32<false><<<dim3((D_EMB + 127) / 128, (SQ + 63) / 64, NB), 256>>>(
        S, normX, att, SQ, D_EMB, SK,
        (size_t)SQ * SK, (size_t)SK * D_EMB, (size_t)SQ * D_EMB, 1.f);

    // 3) MLP (D -> 4 -> D, exact GELU)
    mlp_kernel<<<NB * SQ, 256>>>(att, fc1w, fc1b, fc2w, fc2b, cross);

    // 4) LN(cross) then self-attention
    ln_kernel<<<NB * SQ, 256>>>(cross, n3w, n3b, normC);
    gemm_tf32<true><<<dim3((SQ + 127) / 128, (SQ + 63) / 64, NB), 256>>>(
        normC, normC, S2, SQ, SQ, D_EMB,
        (size_t)SQ * D_EMB, (size_t)SQ * D_EMB, (size_t)SQ * SQ, scale);
    softmax_kernel<<<NB * SQ, 256>>>(S2, SQ);
    gemm_tf32<false><<<dim3((D_EMB + 127) / 128, (SQ + 63) / 64, NB), 256>>>(
        S2, normC, selfa, SQ, D_EMB, SQ,
        (size_t)SQ * SQ, (size_t)SQ * D_EMB, (size_t)SQ * D_EMB, 1.f);

    // 5) out = normQ + g2 * (cross + g1 * self)
    final_kernel<<<NB * SQ, 256>>>(normQ, cross, selfa, g1, g2, (float*)d_out);
}

// round 2
// speedup vs baseline: 1.7508x; 1.7508x over previous
#include <cuda_runtime.h>
#include <mma.h>
#include <math.h>
#include <stdint.h>

using namespace nvcuda;

#define D_EMB 1024
#define NB 8
#define SQ 577
#define SK 13271
#define SKP 13312      // SK padded to 128
#define ROWP 640       // SQ padded to 128
#define SQP 640        // self-attn K padded
#define LNEPS 1e-5f

// ---------------- scratch (__device__ globals) ------------------------------
__device__ float g_normX[(size_t)NB * SK * D_EMB];    // LN(input)  compact
__device__ float g_normQ[(size_t)NB * SQ * D_EMB];    // LN(query)  compact
__device__ float g_S   [(size_t)NB * ROWP * SKP];     // cross scores/probs, padded
__device__ float g_att [(size_t)NB * ROWP * D_EMB];   // attended, padded rows
__device__ float g_cross[(size_t)NB * SQ * D_EMB];    // MLP out, compact
__device__ float g_normC[(size_t)NB * SQ * D_EMB];    // LN(cross), compact
__device__ float g_S2  [(size_t)NB * ROWP * SQP];     // self scores/probs, padded
__device__ float g_self[(size_t)NB * ROWP * D_EMB];   // self attended, padded rows

// ---------------- reductions (blockDim == 256) ------------------------------
__device__ __forceinline__ float block_sum(float v, float* red) {
    #pragma unroll
    for (int o = 16; o > 0; o >>= 1) v += __shfl_xor_sync(0xffffffffu, v, o);
    int w = threadIdx.x >> 5;
    if ((threadIdx.x & 31) == 0) red[w] = v;
    __syncthreads();
    float s = 0.f;
    #pragma unroll
    for (int i = 0; i < 8; i++) s += red[i];
    __syncthreads();
    return s;
}
__device__ __forceinline__ float block_max(float v, float* red) {
    #pragma unroll
    for (int o = 16; o > 0; o >>= 1) v = fmaxf(v, __shfl_xor_sync(0xffffffffu, v, o));
    int w = threadIdx.x >> 5;
    if ((threadIdx.x & 31) == 0) red[w] = v;
    __syncthreads();
    float s = -INFINITY;
    #pragma unroll
    for (int i = 0; i < 8; i++) s = fmaxf(s, red[i]);
    __syncthreads();
    return s;
}

// ---------------- layernorm (tf32-truncated output) -------------------------
__global__ void ln_kernel(const float* __restrict__ in, const float* __restrict__ w,
                          const float* __restrict__ b, float* __restrict__ out) {
    __shared__ float red[8];
    size_t row = blockIdx.x;
    float4 v = ((const float4*)(in + row * D_EMB))[threadIdx.x];
    float mean = block_sum(v.x + v.y + v.z + v.w, red) * (1.f / D_EMB);
    float dx = v.x - mean, dy = v.y - mean, dz = v.z - mean, dw = v.w - mean;
    float var = block_sum(dx*dx + dy*dy + dz*dz + dw*dw, red) * (1.f / D_EMB);
    float inv = rsqrtf(var + LNEPS);
    float4 w4 = ((const float4*)w)[threadIdx.x];
    float4 b4 = ((const float4*)b)[threadIdx.x];
    float4 o;
    o.x = wmma::__float_to_tf32(dx * inv * w4.x + b4.x);
    o.y = wmma::__float_to_tf32(dy * inv * w4.y + b4.y);
    o.z = wmma::__float_to_tf32(dz * inv * w4.z + b4.z);
    o.w = wmma::__float_to_tf32(dw * inv * w4.w + b4.w);
    ((float4*)(out + row * D_EMB))[threadIdx.x] = o;
}

// ---------------- softmax: row cached in smem, pads zeroed ------------------
__global__ void softmax_kernel(float* __restrict__ S, int n, int np, int sq, int rowp) {
    extern __shared__ float buf[];
    __shared__ float red[8];
    int b = blockIdx.x / sq, r = blockIdx.x % sq;
    float* p = S + ((size_t)b * rowp + r) * np;
    float m = -INFINITY;
    for (int i = threadIdx.x; i < n; i += 256) { float v = p[i]; buf[i] = v; m = fmaxf(m, v); }
    m = block_max(m, red);
    float s = 0.f;
    for (int i = threadIdx.x; i < n; i += 256) { float e = __expf(buf[i] - m); buf[i] = e; s += e; }
    s = block_sum(s, red);
    float inv = 1.f / s;
    for (int i = threadIdx.x; i < n; i += 256) p[i] = wmma::__float_to_tf32(buf[i] * inv);
    for (int i = n + threadIdx.x; i < np; i += 256) p[i] = 0.f;
}

// ---------------- cp.async helpers ------------------------------------------
__device__ __forceinline__ void cp16(float* dst, const float* src, bool pred) {
    uint32_t d = (uint32_t)__cvta_generic_to_shared(dst);
    int sz = pred ? 16 : 0;
    asm volatile("cp.async.cg.shared.global [%0], [%1], 16, %2;\n" :: "r"(d), "l"(src), "r"(sz));
}

// ---------------- tf32 wmma GEMM, 128x128x32, cp.async double-buffered ------
// C[m][n] = alpha * sum_k A[m][k] * Bop[k][n]
// TRANS_B=true : B is [N,K] row-major (Bop = B^T)
// TRANS_B=false: B is [K,N] row-major
// A row stride == K (padded), C fully padded (direct stores), operand edges zfilled.
template <bool TRANS_B>
__global__ __launch_bounds__(256, 2)
void gemm_tf32(const float* __restrict__ A, const float* __restrict__ B, float* __restrict__ C,
               int Mreal, int Nreal, int K, int Kreal, int ldb_n, int ldc,
               size_t sA, size_t sB, size_t sC, float alpha) {
    extern __shared__ float sm[];
    float* Asm[2] = { sm, sm + 4608 };              // 128 x 36
    float* Bsm[2] = { sm + 9216, sm + 13824 };      // 128x36 (T) or 32x132 (N)

    A += blockIdx.z * sA;  B += blockIdx.z * sB;  C += blockIdx.z * sC;
    const int m0 = blockIdx.y * 128, n0 = blockIdx.x * 128;
    const int tid = threadIdx.x, warp = tid >> 5;
    const int wm = warp >> 1, wn = warp & 1;        // 4x2 warps, 32m x 64n each

    wmma::fragment<wmma::accumulator, 16, 16, 8, float> acc[2][4];
    #pragma unroll
    for (int i = 0; i < 2; i++)
        #pragma unroll
        for (int j = 0; j < 4; j++) wmma::fill_fragment(acc[i][j], 0.f);

    auto load_tile = [&](int kt, int bufi) {
        const int k0 = kt * 32;
        float* as = Asm[bufi]; float* bs = Bsm[bufi];
        #pragma unroll
        for (int i = 0; i < 4; i++) {
            int idx = tid + i * 256;
            int r = idx >> 3, v = (idx & 7) * 4;
            int gr = m0 + r;
            cp16(as + r * 36 + v, A + (size_t)gr * K + k0 + v, gr < Mreal);
        }
        if (TRANS_B) {
            #pragma unroll
            for (int i = 0; i < 4; i++) {
                int idx = tid + i * 256;
                int r = idx >> 3, v = (idx & 7) * 4;
                int gn = n0 + r;
                cp16(bs + r * 36 + v, B + (size_t)gn * K + k0 + v, gn < Nreal);
            }
        } else {
            #pragma unroll
            for (int i = 0; i < 4; i++) {
                int idx = tid + i * 256;
                int kk = idx >> 5, v = (idx & 31) * 4;
                int gk = k0 + kk;
                cp16(bs + kk * 132 + v, B + (size_t)gk * ldb_n + n0 + v, gk < Kreal);
            }
        }
        asm volatile("cp.async.commit_group;\n");
    };

    const int KT = K / 32;
    load_tile(0, 0);
    for (int kt = 0; kt < KT; kt++) {
        const int bufi = kt & 1;
        if (kt + 1 < KT) {
            load_tile(kt + 1, bufi ^ 1);
            asm volatile("cp.async.wait_group 1;\n");
        } else {
            asm volatile("cp.async.wait_group 0;\n");
        }
        __syncthreads();
        float* as = Asm[bufi]; float* bs = Bsm[bufi];
        #pragma unroll
        for (int ks = 0; ks < 4; ks++) {
            wmma::fragment<wmma::matrix_a, 16, 16, 8, wmma::precision::tf32, wmma::row_major> af[2];
            #pragma unroll
            for (int i = 0; i < 2; i++)
                wmma::load_matrix_sync(af[i], as + (wm * 32 + i * 16) * 36 + ks * 8, 36);
            if (TRANS_B) {
                wmma::fragment<wmma::matrix_b, 16, 16, 8, wmma::precision::tf32, wmma::col_major> bf[4];
                #pragma unroll
                for (int j = 0; j < 4; j++)
                    wmma::load_matrix_sync(bf[j], bs + (wn * 64 + j * 16) * 36 + ks * 8, 36);
                #pragma unroll
                for (int i = 0; i < 2; i++)
                    #pragma unroll
                    for (int j = 0; j < 4; j++)
                        wmma::mma_sync(acc[i][j], af[i], bf[j], acc[i][j]);
            } else {
                wmma::fragment<wmma::matrix_b, 16, 16, 8, wmma::precision::tf32, wmma::row_major> bf[4];
                #pragma unroll
                for (int j = 0; j < 4; j++)
                    wmma::load_matrix_sync(bf[j], bs + ks * 8 * 132 + wn * 64 + j * 16, 132);
                #pragma unroll
                for (int i = 0; i < 2; i++)
                    #pragma unroll
                    for (int j = 0; j < 4; j++)
                        wmma::mma_sync(acc[i][j], af[i], bf[j], acc[i][j]);
            }
        }
        __syncthreads();
    }

    #pragma unroll
    for (int i = 0; i < 2; i++)
        #pragma unroll
        for (int j = 0; j < 4; j++) {
            #pragma unroll
            for (int e = 0; e < 8; e++) acc[i][j].x[e] *= alpha;
            int rg = m0 + wm * 32 + i * 16, cg = n0 + wn * 64 + j * 16;
            wmma::store_matrix_sync(C + (size_t)rg * ldc + cg, acc[i][j], ldc, wmma::mem_row_major);
        }
}

// ---------------- fused MLP (D->4->D, exact-erf GELU) -----------------------
__global__ void mlp_kernel(const float* __restrict__ att, const float* __restrict__ w1,
                           const float* __restrict__ b1, const float* __restrict__ w2,
                           const float* __restrict__ b2, float* __restrict__ out) {
    __shared__ float red[4][8];
    __shared__ float hh[4];
    int b = blockIdx.x / SQ, r = blockIdx.x % SQ;
    float4 v = ((const float4*)(att + ((size_t)b * ROWP + r) * D_EMB))[threadIdx.x];
    #pragma unroll
    for (int h = 0; h < 4; h++) {
        float4 w = ((const float4*)(w1 + (size_t)h * D_EMB))[threadIdx.x];
        float p = v.x * w.x + v.y * w.y + v.z * w.z + v.w * w.w;
        #pragma unroll
        for (int o = 16; o > 0; o >>= 1) p += __shfl_xor_sync(0xffffffffu, p, o);
        if ((threadIdx.x & 31) == 0) red[h][threadIdx.x >> 5] = p;
    }
    __syncthreads();
    if (threadIdx.x < 4) {
        float s = b1[threadIdx.x];
        #pragma unroll
        for (int i = 0; i < 8; i++) s += red[threadIdx.x][i];
        hh[threadIdx.x] = 0.5f * s * (1.f + erff(s * 0.70710678118654752f));
    }
    __syncthreads();
    float h0 = hh[0], h1 = hh[1], h2 = hh[2], h3 = hh[3];
    int d = threadIdx.x * 4;
    float4 wa = ((const float4*)w2)[d + 0];
    float4 wb = ((const float4*)w2)[d + 1];
    float4 wc = ((const float4*)w2)[d + 2];
    float4 wd = ((const float4*)w2)[d + 3];
    float4 o;
    o.x = h0 * wa.x + h1 * wa.y + h2 * wa.z + h3 * wa.w + b2[d + 0];
    o.y = h0 * wb.x + h1 * wb.y + h2 * wb.z + h3 * wb.w + b2[d + 1];
    o.z = h0 * wc.x + h1 * wc.y + h2 * wc.z + h3 * wc.w + b2[d + 2];
    o.w = h0 * wd.x + h1 * wd.y + h2 * wd.z + h3 * wd.w + b2[d + 3];
    ((float4*)(out + ((size_t)b * SQ + r) * D_EMB))[threadIdx.x] = o;
}

// ---------------- final combine ---------------------------------------------
__global__ void final_kernel(const float* __restrict__ normQ, const float* __restrict__ cross,
                             const float* __restrict__ selfa, const float* __restrict__ g1,
                             const float* __restrict__ g2, float* __restrict__ out) {
    int b = blockIdx.x / SQ, r = blockIdx.x % SQ;
    size_t ci = ((size_t)b * SQ + r) * 256 + threadIdx.x;    // float4 index, compact
    size_t si = ((size_t)b * ROWP + r) * 256 + threadIdx.x;  // float4 index, padded
    float4 q = ((const float4*)normQ)[ci];
    float4 c = ((const float4*)cross)[ci];
    float4 s = ((const float4*)selfa)[si];
    float4 a = ((const float4*)g1)[threadIdx.x];
    float4 bb = ((const float4*)g2)[threadIdx.x];
    float4 o;
    o.x = q.x + bb.x * (c.x + a.x * s.x);
    o.y = q.y + bb.y * (c.y + a.y * s.y);
    o.z = q.z + bb.z * (c.z + a.z * s.z);
    o.w = q.w + bb.w * (c.w + a.w * s.w);
    ((float4*)out)[ci] = o;
}

// ---------------- launch ------------------------------------------------------
extern "C" void kernel_launch(void* const* d_in, const int* in_sizes, int n_in,
                              void* d_out, int out_size) {
    const float* input_features = (const float*)d_in[0];
    const float* query_feature  = (const float*)d_in[1];
    const float* n1w = (const float*)d_in[2];
    const float* n1b = (const float*)d_in[3];
    const float* n2w = (const float*)d_in[4];
    const float* n2b = (const float*)d_in[5];
    const float* n3w = (const float*)d_in[6];
    const float* n3b = (const float*)d_in[7];
    const float* g1  = (const float*)d_in[8];
    const float* g2  = (const float*)d_in[9];
    const float* fc1w = (const float*)d_in[10];
    const float* fc1b = (const float*)d_in[11];
    const float* fc2w = (const float*)d_in[12];
    const float* fc2b = (const float*)d_in[13];

    float *normX, *normQ, *S, *att, *cross, *normC, *S2, *selfa;
    cudaGetSymbolAddress((void**)&normX, g_normX);
    cudaGetSymbolAddress((void**)&normQ, g_normQ);
    cudaGetSymbolAddress((void**)&S,     g_S);
    cudaGetSymbolAddress((void**)&att,   g_att);
    cudaGetSymbolAddress((void**)&cross, g_cross);
    cudaGetSymbolAddress((void**)&normC, g_normC);
    cudaGetSymbolAddress((void**)&S2,    g_S2);
    cudaGetSymbolAddress((void**)&selfa, g_self);

    const int GEMM_SMEM = 18432 * 4;
    cudaFuncSetAttribute((const void*)gemm_tf32<true>,  cudaFuncAttributeMaxDynamicSharedMemorySize, GEMM_SMEM);
    cudaFuncSetAttribute((const void*)gemm_tf32<false>, cudaFuncAttributeMaxDynamicSharedMemorySize, GEMM_SMEM);
    cudaFuncSetAttribute((const void*)softmax_kernel,   cudaFuncAttributeMaxDynamicSharedMemorySize, SKP * 4);

    const float scale = 0.03125f;   // 1024^-0.5

    // 1) layernorms
    ln_kernel<<<NB * SK, 256>>>(input_features, n1w, n1b, normX);
    ln_kernel<<<NB * SQ, 256>>>(query_feature,  n2w, n2b, normQ);

    // 2) cross attention
    gemm_tf32<true><<<dim3(SKP / 128, ROWP / 128, NB), 256, GEMM_SMEM>>>(
        normQ, normX, S, SQ, SK, D_EMB, D_EMB, 0, SKP,
        (size_t)SQ * D_EMB, (size_t)SK * D_EMB, (size_t)ROWP * SKP, scale);
    softmax_kernel<<<NB * SQ, 256, SKP * 4>>>(S, SK, SKP, SQ, ROWP);
    gemm_tf32<false><<<dim3(D_EMB / 128, ROWP / 128, NB), 256, GEMM_SMEM>>>(
        S, normX, att, SQ, D_EMB, SKP, SK, D_EMB, D_EMB,
        (size_t)ROWP * SKP, (size_t)SK * D_EMB, (size_t)ROWP * D_EMB, 1.f);

    // 3) MLP
    mlp_kernel<<<NB * SQ, 256>>>(att, fc1w, fc1b, fc2w, fc2b, cross);

    // 4) LN + self attention
    ln_kernel<<<NB * SQ, 256>>>(cross, n3w, n3b, normC);
    gemm_tf32<true><<<dim3(SQP / 128, ROWP / 128, NB), 256, GEMM_SMEM>>>(
        normC, normC, S2, SQ, SQ, D_EMB, D_EMB, 0, SQP,
        (size_t)SQ * D_EMB, (size_t)SQ * D_EMB, (size_t)ROWP * SQP, scale);
    softmax_kernel<<<NB * SQ, 256, SQP * 4>>>(S2, SQ, SQP, SQ, ROWP);
    gemm_tf32<false><<<dim3(D_EMB / 128, ROWP / 128, NB), 256, GEMM_SMEM>>>(
        S2, normC, selfa, SQ, D_EMB, SQP, SQ, D_EMB, D_EMB,
        (size_t)ROWP * SQP, (size_t)SQ * D_EMB, (size_t)ROWP * D_EMB, 1.f);

    // 5) combine
    final_kernel<<<NB * SQ, 256>>>(normQ, cross, selfa, g1, g2, (float*)d_out);
}